// round 3
// baseline (speedup 1.0000x reference)
#include <cuda_runtime.h>
#include <cuda_bf16.h>
#include <cstdint>
#include <cstddef>

// Seq2seq GRU encoder/decoder, fp32 persistent-decoder implementation.
// B=4096, F=128, H=256, ISEQ=96, PSEQ=48.
//
//   prep_kernel    : transpose weights into k-major, gate-triplet-interleaved scratch
//   seq2seq_kernel : persistent, 128 CTAs x 32 batch rows:
//                      encoder GRU cell on x_last (h0=0)  -> h_enc (SMEM)
//                      fc + relu                          -> h (SMEM, [m][c])
//                      48 decoder GRU steps, h never leaves SMEM

#define BATCH   4096
#define F_      128
#define H_      256
#define ISEQ    96
#define PSEQ    48
#define MTILE   32
#define XST     36      // k-major smem row stride (floats), multiple of 4 for float4
#define HS2ST   132     // h row-major stride (floats)
#define BUFSZ   6144    // floats per weight-chunk buffer (16 x 384)

// ---------------- device scratch (allocation-free rule) ----------------
__device__ float g_WencT[128 * 768];   // [k][3c+g] of W_ih_enc
__device__ float g_WihT [128 * 384];   // [k][3c+g] of W_ih_dec
__device__ float g_WhhT [128 * 384];   // [k][3c+g] of W_hh_dec
__device__ float g_WfcT [256 * 128];   // [k][c]    of W_fc

// ---------------- helpers ----------------
__device__ __forceinline__ float sigf(float x) { return 1.0f / (1.0f + __expf(-x)); }

__device__ __forceinline__ void cp_async16(float* sdst, const float* gsrc) {
    unsigned sa = (unsigned)__cvta_generic_to_shared(sdst);
    asm volatile("cp.async.cg.shared.global [%0], [%1], 16;" :: "r"(sa), "l"(gsrc));
}
__device__ __forceinline__ void cp_commit() { asm volatile("cp.async.commit_group;"); }
__device__ __forceinline__ void cp_wait1()  { asm volatile("cp.async.wait_group 1;"); }
__device__ __forceinline__ void cp_wait0()  { asm volatile("cp.async.wait_group 0;"); }

// ---------------- prep: weight re-layout ----------------
__global__ void prep_kernel(const float* __restrict__ Wihe,
                            const float* __restrict__ Wihd,
                            const float* __restrict__ Whhd,
                            const float* __restrict__ Wfc) {
    int idx = blockIdx.x * 256 + threadIdx.x;
    if (idx < 98304) {                       // 128 x 768 encoder ih
        int k = idx / 768, s = idx - k * 768;
        int c = s / 3, g = s - 3 * c;
        g_WencT[idx] = Wihe[(g * 256 + c) * 128 + k];
    } else if (idx < 147456) {               // 128 x 384 decoder ih
        int j = idx - 98304;
        int k = j / 384, s = j - k * 384;
        int c = s / 3, g = s - 3 * c;
        g_WihT[j] = Wihd[(g * 128 + c) * 128 + k];
    } else if (idx < 196608) {               // 128 x 384 decoder hh
        int j = idx - 147456;
        int k = j / 384, s = j - k * 384;
        int c = s / 3, g = s - 3 * c;
        g_WhhT[j] = Whhd[(g * 128 + c) * 128 + k];
    } else if (idx < 229376) {               // 256 x 128 fc
        int j = idx - 196608;
        int k = j / 128, c = j - k * 128;
        g_WfcT[j] = Wfc[c * 256 + k];
    }
}

// ---------------- chunk loaders (gmem -> smem, cp.async) ----------------
// 16 x 384 chunk. 256 threads: row = tid>>4, 24 floats each.
__device__ __forceinline__ void load_chunk384(float* dst, const float* src,
                                              int srcStride, int tid) {
    int row = tid >> 4;
    int col = (tid & 15) * 24;
    const float* s = src + (size_t)row * srcStride + col;
    float* d = dst + row * 384 + col;
#pragma unroll
    for (int i = 0; i < 6; i++) cp_async16(d + i * 4, s + i * 4);
}
// 16 x 128 chunk (fc weights).
__device__ __forceinline__ void load_chunk128(float* dst, const float* src, int tid) {
    int row = tid >> 4;
    int col = (tid & 15) * 8;
    const float* s = src + row * 128 + col;
    float* d = dst + row * 128 + col;
    cp_async16(d, s);
    cp_async16(d + 4, s + 4);
}

// Load a [32 x 128] x tile and transpose into xs[k][m] (stride XST).
// Warp = one 16-float f chunk, lanes = batch rows -> conflict-free STS.
__device__ __forceinline__ void load_x_tile(const float* rowbase, int rowStride,
                                            float* xs, int b0, int tid) {
    int m  = tid & 31;
    int f0 = (tid >> 5) * 16;
    const float4* s = (const float4*)(rowbase + (size_t)(b0 + m) * rowStride + f0);
    float4 v0 = s[0], v1 = s[1], v2 = s[2], v3 = s[3];
    float vv[16] = {v0.x, v0.y, v0.z, v0.w, v1.x, v1.y, v1.z, v1.w,
                    v2.x, v2.y, v2.z, v2.w, v3.x, v3.y, v3.z, v3.w};
#pragma unroll
    for (int i = 0; i < 16; i++) xs[(f0 + i) * XST + m] = vv[i];
}

// ---------------- GEMM micro-tiles ----------------
// Thread (tx,ty): rows 4*ty..+3, storage cols 12*tx..+11 (4 gate triplets).
// A k-major [k][m] (stride XST): broadcast float4 reads.
__device__ __forceinline__ void gemm_x_full(const float* __restrict__ A,
                                            const float* __restrict__ Bt,
                                            int tx, int ty, float (&acc)[4][12]) {
#pragma unroll
    for (int k = 0; k < 16; k++) {
        float4 av = *(const float4*)(A + k * XST + 4 * ty);
        const float* bp = Bt + k * 384 + 12 * tx;
        float4 b0 = *(const float4*)(bp);
        float4 b1 = *(const float4*)(bp + 4);
        float4 b2 = *(const float4*)(bp + 8);
        float aa[4]  = {av.x, av.y, av.z, av.w};
        float bb[12] = {b0.x, b0.y, b0.z, b0.w, b1.x, b1.y, b1.z, b1.w,
                        b2.x, b2.y, b2.z, b2.w};
#pragma unroll
        for (int r = 0; r < 4; r++)
#pragma unroll
            for (int j = 0; j < 12; j++)
                acc[r][j] = fmaf(aa[r], bb[j], acc[r][j]);
    }
}

// A from h stored row-major [m][HS2ST]: scalar broadcast reads.
__device__ __forceinline__ void gemm_h_full(const float* __restrict__ hs2, int k0,
                                            const float* __restrict__ Bt,
                                            int tx, int ty, float (&acc)[4][12]) {
#pragma unroll
    for (int k = 0; k < 16; k++) {
        const float* bp = Bt + k * 384 + 12 * tx;
        float4 b0 = *(const float4*)(bp);
        float4 b1 = *(const float4*)(bp + 4);
        float4 b2 = *(const float4*)(bp + 8);
        float bb[12] = {b0.x, b0.y, b0.z, b0.w, b1.x, b1.y, b1.z, b1.w,
                        b2.x, b2.y, b2.z, b2.w};
        float aa[4];
#pragma unroll
        for (int r = 0; r < 4; r++) aa[r] = hs2[(4 * ty + r) * HS2ST + k0 + k];
#pragma unroll
        for (int r = 0; r < 4; r++)
#pragma unroll
            for (int j = 0; j < 12; j++)
                acc[r][j] = fmaf(aa[r], bb[j], acc[r][j]);
    }
}

// Same, but n-gate columns (j%3==2) go to a separate accumulator (for r*h_n).
__device__ __forceinline__ void gemm_h_split(const float* __restrict__ hs2, int k0,
                                             const float* __restrict__ Bt,
                                             int tx, int ty,
                                             float (&acc)[4][12], float (&accn)[4][4]) {
#pragma unroll
    for (int k = 0; k < 16; k++) {
        const float* bp = Bt + k * 384 + 12 * tx;
        float4 b0 = *(const float4*)(bp);
        float4 b1 = *(const float4*)(bp + 4);
        float4 b2 = *(const float4*)(bp + 8);
        float bb[12] = {b0.x, b0.y, b0.z, b0.w, b1.x, b1.y, b1.z, b1.w,
                        b2.x, b2.y, b2.z, b2.w};
        float aa[4];
#pragma unroll
        for (int r = 0; r < 4; r++) aa[r] = hs2[(4 * ty + r) * HS2ST + k0 + k];
#pragma unroll
        for (int r = 0; r < 4; r++)
#pragma unroll
            for (int j = 0; j < 12; j++) {
                if (j % 3 == 2) accn[r][j / 3] = fmaf(aa[r], bb[j], accn[r][j / 3]);
                else            acc[r][j]      = fmaf(aa[r], bb[j], acc[r][j]);
            }
    }
}

// fc GEMM: out 32x128, k chunked by 16. Thread tile 4x4 (cols 4*tx..+3).
__device__ __forceinline__ void gemm_fc(const float* __restrict__ A,
                                        const float* __restrict__ Bt,
                                        int tx, int ty, float (&acc)[4][4]) {
#pragma unroll
    for (int k = 0; k < 16; k++) {
        float4 av = *(const float4*)(A + k * XST + 4 * ty);
        float4 bv = *(const float4*)(Bt + k * 128 + 4 * tx);
        float aa[4] = {av.x, av.y, av.z, av.w};
        float bb[4] = {bv.x, bv.y, bv.z, bv.w};
#pragma unroll
        for (int r = 0; r < 4; r++)
#pragma unroll
            for (int j = 0; j < 4; j++)
                acc[r][j] = fmaf(aa[r], bb[j], acc[r][j]);
    }
}

// ---------------- main persistent kernel ----------------
__global__ void __launch_bounds__(256, 1)
seq2seq_kernel(const float* __restrict__ z_in,
               const float* __restrict__ z_tar,
               const float* __restrict__ bihe,
               const float* __restrict__ bhhe,
               const float* __restrict__ bfc,
               const float* __restrict__ bihd,
               const float* __restrict__ bhhd,
               const int*   __restrict__ tf_ptr,
               float*       __restrict__ out) {
    extern __shared__ float sm[];
    float* Bs  = sm;                       // 2 x 6144 weight chunk buffers
    float* xs  = sm + 2 * BUFSZ;           // 128 x XST   x tile, k-major
    float* hs2 = xs + 128 * XST;           // 32 x HS2ST  h, row-major [m][c]
    float* he  = hs2 + MTILE * HS2ST;      // 256 x XST   h_enc, k-major

    const int tid = threadIdx.x;
    const int tx = tid & 31, ty = tid >> 5;
    const int b0 = blockIdx.x * MTILE;
    const bool tf = (*tf_ptr != 0);

    // ======== encoder: GRU(x_last, h0=0) -> he ========
    load_x_tile(z_in + (size_t)(ISEQ - 1) * F_, ISEQ * F_, xs, b0, tid);

#pragma unroll 1
    for (int cc = 0; cc < 2; cc++) {
        float acc[4][12];
#pragma unroll
        for (int r = 0; r < 4; r++)
#pragma unroll
            for (int j = 0; j < 12; j++) acc[r][j] = 0.0f;

        load_chunk384(Bs, g_WencT + cc * 384, 768, tid);
        cp_commit();
#pragma unroll 1
        for (int ch = 0; ch < 8; ch++) {
            if (ch < 7) {
                load_chunk384(Bs + ((ch + 1) & 1) * BUFSZ,
                              g_WencT + (size_t)(ch + 1) * 16 * 768 + cc * 384, 768, tid);
                cp_commit();
                cp_wait1();
            } else {
                cp_wait0();
            }
            __syncthreads();
            gemm_x_full(xs + ch * 16 * XST, Bs + (ch & 1) * BUFSZ, tx, ty, acc);
            __syncthreads();
        }
        // combine (gh = b_hh since h0 = 0): h_enc = (1-z)*n
#pragma unroll
        for (int cj = 0; cj < 4; cj++) {
            int c = cc * 128 + 4 * tx + cj;
            float br  = bihe[c] + bhhe[c];
            float bz  = bihe[H_ + c] + bhhe[H_ + c];
            float bni = bihe[2 * H_ + c];
            float bnh = bhhe[2 * H_ + c];
#pragma unroll
            for (int r = 0; r < 4; r++) {
                float rr = sigf(acc[r][3 * cj] + br);
                float zz = sigf(acc[r][3 * cj + 1] + bz);
                float nn = tanhf(acc[r][3 * cj + 2] + bni + rr * bnh);
                he[c * XST + 4 * ty + r] = (1.0f - zz) * nn;
            }
        }
    }

    // ======== fc + relu -> hs2 (dec_h0, row-major) ========
    {
        float acc2[4][4];
#pragma unroll
        for (int r = 0; r < 4; r++)
#pragma unroll
            for (int j = 0; j < 4; j++) acc2[r][j] = 0.0f;

        load_chunk128(Bs, g_WfcT, tid);
        cp_commit();
#pragma unroll 1
        for (int ch = 0; ch < 16; ch++) {
            if (ch < 15) {
                load_chunk128(Bs + ((ch + 1) & 1) * BUFSZ, g_WfcT + (ch + 1) * 16 * 128, tid);
                cp_commit();
                cp_wait1();
            } else {
                cp_wait0();
            }
            __syncthreads();
            gemm_fc(he + ch * 16 * XST, Bs + (ch & 1) * BUFSZ, tx, ty, acc2);
            __syncthreads();
        }
#pragma unroll
        for (int r = 0; r < 4; r++) {
            float h0 = fmaxf(acc2[r][0] + bfc[4 * tx + 0], 0.0f);
            float h1 = fmaxf(acc2[r][1] + bfc[4 * tx + 1], 0.0f);
            float h2 = fmaxf(acc2[r][2] + bfc[4 * tx + 2], 0.0f);
            float h3 = fmaxf(acc2[r][3] + bfc[4 * tx + 3], 0.0f);
            *(float4*)(hs2 + (4 * ty + r) * HS2ST + 4 * tx) = make_float4(h0, h1, h2, h3);
        }
    }

    // ======== decoder: 48 GRU steps, h resident in SMEM ========
    float br_[4], bz_[4], bni_[4], bnh_[4];
#pragma unroll
    for (int cj = 0; cj < 4; cj++) {
        int c = 4 * tx + cj;
        br_[cj]  = bihd[c] + bhhd[c];
        bz_[cj]  = bihd[F_ + c] + bhhd[F_ + c];
        bni_[cj] = bihd[2 * F_ + c];
        bnh_[cj] = bhhd[2 * F_ + c];
    }

#pragma unroll 1
    for (int t = 0; t < PSEQ; t++) {
        // x_0 = x_last (already in xs). TF: x_t = z_tar[:,t-1,:]. Non-TF: x_t = h_{t-1}.
        if (t > 0 && tf)
            load_x_tile(z_tar + (size_t)(t - 1) * F_, PSEQ * F_, xs, b0, tid);
        const bool gi_x = (t == 0) || tf;

        float acc[4][12];
        float accn[4][4];
#pragma unroll
        for (int r = 0; r < 4; r++) {
#pragma unroll
            for (int j = 0; j < 12; j++) acc[r][j] = 0.0f;
#pragma unroll
            for (int j = 0; j < 4; j++)  accn[r][j] = 0.0f;
        }

        // 16 weight chunks: 0..7 = W_ih (gi), 8..15 = W_hh (gh), double-buffered.
        load_chunk384(Bs, g_WihT, 384, tid);
        cp_commit();
#pragma unroll 1
        for (int ch = 0; ch < 16; ch++) {
            if (ch < 15) {
                const float* src = (ch + 1 < 8)
                    ? g_WihT + (size_t)(ch + 1) * 16 * 384
                    : g_WhhT + (size_t)(ch + 1 - 8) * 16 * 384;
                load_chunk384(Bs + ((ch + 1) & 1) * BUFSZ, src, 384, tid);
                cp_commit();
                cp_wait1();
            } else {
                cp_wait0();
            }
            __syncthreads();
            const float* Bt = Bs + (ch & 1) * BUFSZ;
            if (ch < 8) {
                if (gi_x) gemm_x_full(xs + ch * 16 * XST, Bt, tx, ty, acc);
                else      gemm_h_full(hs2, ch * 16, Bt, tx, ty, acc);
            } else {
                gemm_h_split(hs2, (ch - 8) * 16, Bt, tx, ty, acc, accn);
            }
            __syncthreads();
        }

        // GRU combine; write h to out and back into hs2 (exclusive per thread).
#pragma unroll
        for (int r = 0; r < 4; r++) {
            float4 hp = *(const float4*)(hs2 + (4 * ty + r) * HS2ST + 4 * tx);
            float hprev[4] = {hp.x, hp.y, hp.z, hp.w};
            float hn[4];
#pragma unroll
            for (int cj = 0; cj < 4; cj++) {
                float rr = sigf(acc[r][3 * cj] + br_[cj]);
                float zz = sigf(acc[r][3 * cj + 1] + bz_[cj]);
                float nn = tanhf(acc[r][3 * cj + 2] + bni_[cj]
                                 + rr * (accn[r][cj] + bnh_[cj]));
                hn[cj] = (1.0f - zz) * nn + zz * hprev[cj];
            }
            float4 o = make_float4(hn[0], hn[1], hn[2], hn[3]);
            *(float4*)(out + ((size_t)(b0 + 4 * ty + r) * PSEQ + t) * F_ + 4 * tx) = o;
            *(float4*)(hs2 + (4 * ty + r) * HS2ST + 4 * tx) = o;
        }
        // next iteration's first in-loop __syncthreads orders these hs2 writes
        // before any cross-thread gemm_h reads.
    }
}

// ---------------- launch ----------------
extern "C" void kernel_launch(void* const* d_in, const int* in_sizes, int n_in,
                              void* d_out, int out_size) {
    const float* z_in  = (const float*)d_in[0];
    const float* z_tar = (const float*)d_in[1];
    const float* Wihe  = (const float*)d_in[2];
    // d_in[3] = W_hh_enc: unused (encoder h0 = 0)
    const float* bihe  = (const float*)d_in[4];
    const float* bhhe  = (const float*)d_in[5];
    const float* Wfc   = (const float*)d_in[6];
    const float* bfc   = (const float*)d_in[7];
    const float* Wihd  = (const float*)d_in[8];
    const float* Whhd  = (const float*)d_in[9];
    const float* bihd  = (const float*)d_in[10];
    const float* bhhd  = (const float*)d_in[11];
    const int*   tf    = (const int*)d_in[12];
    float* out = (float*)d_out;

    prep_kernel<<<896, 256>>>(Wihe, Wihd, Whhd, Wfc);

    const int SMEM = (2 * BUFSZ + 128 * XST + MTILE * HS2ST + 256 * XST) * 4;  // 121344 B
    cudaFuncSetAttribute(seq2seq_kernel, cudaFuncAttributeMaxDynamicSharedMemorySize, SMEM);
    seq2seq_kernel<<<128, 256, SMEM>>>(z_in, z_tar, bihe, bhhe, bfc,
                                       bihd, bhhd, tf, out);
}